// round 14
// baseline (speedup 1.0000x reference)
#include <cuda_runtime.h>
#include <cstdint>

#define D    64
#define BM   128
#define BN   128
#define PAD  72          // words; 72 mod 32 == 8 -> conflict-free LDS.64 fragment phases
#define NROWS 8192

__device__ float g_sq1[NROWS];
__device__ float g_sq2[NROWS];

// ---------------------------------------------------------------------------
__device__ __forceinline__ uint32_t f2tf32(float f) {
    uint32_t u;
    asm("cvt.rna.tf32.f32 %0, %1;" : "=r"(u) : "f"(f));
    return u;
}
__device__ __forceinline__ float tf32val(float f) {
    return __uint_as_float(f2tf32(f));
}

// ---------------------------------------------------------------------------
// Warp-per-row norms of both inputs (tf32-rounded, self-consistent with MMA).
// ---------------------------------------------------------------------------
__global__ void norm_kernel(const float* __restrict__ x1,
                            const float* __restrict__ x2) {
    const int w = (blockIdx.x * blockDim.x + threadIdx.x) >> 5;
    const int lane = threadIdx.x & 31;
    const float* x = (w < NROWS) ? x1 : x2;
    const int row = w & (NROWS - 1);
    float2 v = *(const float2*)(x + (size_t)row * D + lane * 2);
    float a = tf32val(v.x), b = tf32val(v.y);
    float s = fmaf(a, a, b * b);
#pragma unroll
    for (int o = 16; o; o >>= 1)
        s += __shfl_xor_sync(0xFFFFFFFF, s, o);
    if (lane == 0) {
        if (w < NROWS) g_sq1[row] = s; else g_sq2[row] = s;
    }
}

// ---------------------------------------------------------------------------
// 128x128 tile per CTA, 8 warps (2x4), warp tile 64x32, 2 CTAs/SM (R13 core).
// Epilogue: warp-PRIVATE 4KB transpose buffer (no CTA barrier), two 32x32
// passes; swizzle col ^ 8*(row&3); STS.64 / LDS.128 conflict-free; STG.128
// lands 4 dense 128B lines per instruction.
// ---------------------------------------------------------------------------
__global__ __launch_bounds__(256, 2)
void dist_kernel(const float* __restrict__ x1, const float* __restrict__ x2,
                 float* __restrict__ out, int M) {
    extern __shared__ uint32_t smem[];
    uint32_t* sa = smem;              // [BM][PAD] interleaved tf32 bits
    uint32_t* sb = smem + BM * PAD;   // [BN][PAD]

    const int n0  = blockIdx.y * BM;
    const int m0  = blockIdx.x * BN;
    const int tid = threadIdx.x;
    const int wid = tid >> 5;
    const int lane = tid & 31;
    const int wm = wid >> 2;          // 0..1 : 64-row band
    const int wn = wid & 3;           // 0..3 : 32-col band
    const int g  = lane >> 2;         // 0..7
    const int q  = lane & 3;          // 0..3

    float* buf = (float*)(smem + 2 * BM * PAD) + wid * 1024;  // 32x32 floats

    // ---- stage tiles: 2x LDG.128 per (row, 8-col block), K-interleaved STS ----
#pragma unroll
    for (int it = 0; it < 4; ++it) {
        int idx = tid + it * 256;              // 0..1023 (row, block) pairs
        int r = idx >> 3, b = idx & 7;
        const float4* pa = (const float4*)(x1 + (size_t)(n0 + r) * D + b * 8);
        const float4* pb = (const float4*)(x2 + (size_t)(m0 + r) * D + b * 8);
        float4 a0 = pa[0], a1 = pa[1];
        float4 b0 = pb[0], b1 = pb[1];
        int base = r * PAD + b * 8 + 4 * (b >> 2);
        *(uint4*)(sa + base) =
            make_uint4(f2tf32(a0.x), f2tf32(a1.x), f2tf32(a0.y), f2tf32(a1.y));
        *(uint4*)(sa + base + 4) =
            make_uint4(f2tf32(a0.z), f2tf32(a1.z), f2tf32(a0.w), f2tf32(a1.w));
        *(uint4*)(sb + base) =
            make_uint4(f2tf32(b0.x), f2tf32(b1.x), f2tf32(b0.y), f2tf32(b1.y));
        *(uint4*)(sb + base + 4) =
            make_uint4(f2tf32(b0.z), f2tf32(b1.z), f2tf32(b0.w), f2tf32(b1.w));
    }
    __syncthreads();

    float acc[4][4][4];
#pragma unroll
    for (int i = 0; i < 4; ++i)
#pragma unroll
        for (int j = 0; j < 4; ++j)
#pragma unroll
            for (int c = 0; c < 4; ++c) acc[i][j][c] = 0.f;

    // ---- K loop: 8 steps of k=8, paired LDS.64 fragment loads ----
#pragma unroll
    for (int ks = 0; ks < 8; ++ks) {
        const int kbase = 8 * ks + 4 * (ks >> 2) + 2 * q;

        uint2 bfr[4];                 // .x = k(q), .y = k(q+4)
#pragma unroll
        for (int nf = 0; nf < 4; ++nf)
            bfr[nf] = *(const uint2*)(sb + (wn * 32 + nf * 8 + g) * PAD + kbase);

#pragma unroll
        for (int mf = 0; mf < 4; ++mf) {
            const int r = wm * 64 + mf * 16 + g;
            uint2 alo = *(const uint2*)(sa + r * PAD + kbase);        // a0, a2
            uint2 ahi = *(const uint2*)(sa + (r + 8) * PAD + kbase);  // a1, a3
#pragma unroll
            for (int nf = 0; nf < 4; ++nf) {
                asm volatile(
                    "mma.sync.aligned.m16n8k8.row.col.f32.tf32.tf32.f32 "
                    "{%0,%1,%2,%3}, {%4,%5,%6,%7}, {%8,%9}, {%0,%1,%2,%3};"
                    : "+f"(acc[mf][nf][0]), "+f"(acc[mf][nf][1]),
                      "+f"(acc[mf][nf][2]), "+f"(acc[mf][nf][3])
                    : "r"(alo.x), "r"(ahi.x), "r"(alo.y), "r"(ahi.y),
                      "r"(bfr[nf].x), "r"(bfr[nf].y));
            }
        }
    }

    // ---- epilogue: two 32x32 transpose passes through warp-private buffer ----
    const int swz = 8 * (g & 3);              // row&3 == g&3 for rows 16mf+g(+8)
    const int rr  = lane >> 3;                // readback: row offset 0..3
    const int jr  = lane & 7;                 // readback: float4 index 0..7

#pragma unroll
    for (int h = 0; h < 2; ++h) {
        // phase 1: d2 -> swizzled buffer (rows 0..31 = mh*16 + g (+8))
#pragma unroll
        for (int mh = 0; mh < 2; ++mh) {
            const int mf = h * 2 + mh;
            const int grow = n0 + wm * 64 + mf * 16 + g;
            const float s1a = __ldg(&g_sq1[grow]);
            const float s1b = __ldg(&g_sq1[grow + 8]);
            const int rl0 = mh * 16 + g;
#pragma unroll
            for (int nf = 0; nf < 4; ++nf) {
                const int cidx = wn * 32 + nf * 8 + 2 * q;
                const float2 s2 = __ldg((const float2*)&g_sq2[m0 + cidx]);
                const int cs = (nf * 8 + 2 * q) ^ swz;
                float2 ra, rb;
                ra.x = fmaxf(fmaf(-2.f, acc[mf][nf][0], s1a + s2.x), 0.f);
                ra.y = fmaxf(fmaf(-2.f, acc[mf][nf][1], s1a + s2.y), 0.f);
                rb.x = fmaxf(fmaf(-2.f, acc[mf][nf][2], s1b + s2.x), 0.f);
                rb.y = fmaxf(fmaf(-2.f, acc[mf][nf][3], s1b + s2.y), 0.f);
                *(float2*)(buf + rl0 * 32 + cs)       = ra;
                *(float2*)(buf + (rl0 + 8) * 32 + cs) = rb;
            }
        }
        __syncwarp();

        // phase 2: de-swizzled readback -> dense STG.128
#pragma unroll
        for (int t = 0; t < 8; ++t) {
            const int rl = t * 4 + rr;        // buffer row 0..31
            const float4 v = *(const float4*)(buf + rl * 32
                                              + ((4 * jr) ^ (8 * (rl & 3))));
            __stcs((float4*)(out + (size_t)(n0 + wm * 64 + h * 32 + rl) * M
                                  + m0 + wn * 32 + 4 * jr), v);
        }
        __syncwarp();   // buffer reused by next pass
    }
}

// ---------------------------------------------------------------------------
extern "C" void kernel_launch(void* const* d_in, const int* in_sizes, int n_in,
                              void* d_out, int out_size) {
    const float* x1 = (const float*)d_in[0];
    const float* x2 = (const float*)d_in[1];
    float* out = (float*)d_out;

    const int N = in_sizes[0] / D;   // 8192
    const int M = in_sizes[1] / D;   // 8192

    const int smem_bytes = 2 * BM * PAD * sizeof(uint32_t)   // 73728
                         + 8 * 1024 * sizeof(float);          // +32768 = 106496
    cudaFuncSetAttribute(dist_kernel,
                         cudaFuncAttributeMaxDynamicSharedMemorySize, smem_bytes);

    norm_kernel<<<2 * NROWS * 32 / 256, 256>>>(x1, x2);

    dim3 grid(M / BN, N / BM);
    dist_kernel<<<grid, 256, smem_bytes>>>(x1, x2, out, M);
}

// round 15
// speedup vs baseline: 1.0528x; 1.0528x over previous
#include <cuda_runtime.h>
#include <cstdint>

#define D    64
#define BM   128
#define BN   128
#define PAD  72          // words; 72 mod 32 == 8 -> conflict-free LDS.64 fragment phases
#define NROWS 8192

__device__ float g_sq1[NROWS];
__device__ float g_sq2[NROWS];
__device__ float g_x1t[NROWS * D];   // tf32-rounded, K-interleaved
__device__ float g_x2t[NROWS * D];

// ---------------------------------------------------------------------------
__device__ __forceinline__ uint32_t f2tf32(float f) {
    uint32_t u;
    asm("cvt.rna.tf32.f32 %0, %1;" : "=r"(u) : "f"(f));
    return u;
}
__device__ __forceinline__ float tf32val(float f) {
    return __uint_as_float(f2tf32(f));
}
__device__ __forceinline__ uint32_t smem_u32(const void* p) {
    uint32_t a;
    asm("{ .reg .u64 t; cvta.to.shared.u64 t, %1; cvt.u32.u64 %0, t; }" : "=r"(a) : "l"(p));
    return a;
}
#define CP16(dst_u32, src_ptr) \
    asm volatile("cp.async.cg.shared.global [%0], [%1], 16;" \
                 :: "r"(dst_u32), "l"(src_ptr) : "memory")

// ---------------------------------------------------------------------------
// Prep: tf32(RNA)-round both inputs into K-interleaved layout + row norms.
// Warp per row. Interleaved word w of a row holds original k:
//   b = w>>3, pos = w&7 ->  k = 8b + (pos>>1) + 4*(pos&1)
// i.e. per 8-block order [k0,k4,k1,k5,k2,k6,k3,k7] (matches the mainloop's
// paired LDS.64 fragment fetch).
// ---------------------------------------------------------------------------
__global__ void prep_kernel(const float* __restrict__ x1,
                            const float* __restrict__ x2) {
    const int gw = (blockIdx.x * blockDim.x + threadIdx.x) >> 5;  // row id
    const int lane = threadIdx.x & 31;
    const int row = gw & (NROWS - 1);
    const float* src = (gw < NROWS) ? x1 : x2;
    float* dst       = (gw < NROWS) ? g_x1t : g_x2t;
    float* nrm       = (gw < NROWS) ? g_sq1 : g_sq2;

    const int k0 = 8 * (lane >> 2) + (lane & 3);      // lane covers k0, k0+4
    float a = tf32val(src[(size_t)row * D + k0]);
    float b = tf32val(src[(size_t)row * D + k0 + 4]);
    *(float2*)(dst + (size_t)row * D + 2 * lane) = make_float2(a, b);

    float s = fmaf(a, a, b * b);
#pragma unroll
    for (int o = 16; o; o >>= 1)
        s += __shfl_xor_sync(0xFFFFFFFF, s, o);
    if (lane == 0) nrm[row] = s;
}

// ---------------------------------------------------------------------------
// 128x128 tile per CTA, 8 warps (2x4), warp tile 64x32, 2 CTAs/SM.
// Staging: pure cp.async from pre-converted interleaved arrays (no LDG wait,
// no cvt). Mainloop: paired LDS.64 fragment loads + m16n8k8 tf32 MMA (R13).
// ---------------------------------------------------------------------------
__global__ __launch_bounds__(256, 2)
void dist_kernel(float* __restrict__ out, int M) {
    extern __shared__ uint32_t smem[];
    uint32_t* sa = smem;              // [BM][PAD] interleaved tf32 bits
    uint32_t* sb = smem + BM * PAD;   // [BN][PAD]

    const int n0  = blockIdx.y * BM;
    const int m0  = blockIdx.x * BN;
    const int tid = threadIdx.x;
    const int wid = tid >> 5;
    const int lane = tid & 31;
    const int wm = wid >> 2;          // 0..1 : 64-row band
    const int wn = wid & 3;           // 0..3 : 32-col band
    const int g  = lane >> 2;         // 0..7
    const int q  = lane & 3;          // 0..3

    // ---- stage tiles: 16B cp.async chunks into skewed rows ----
    // row layout: words [0..32) at base, words [32..64) at base+4 (skew)
    {
        const uint32_t sAu = smem_u32(sa);
        const uint32_t sBu = smem_u32(sb);
#pragma unroll
        for (int it = 0; it < 8; ++it) {
            int idx = tid + it * 256;          // 0..2047: (row, chunk)
            int r = idx >> 4;
            int w = (idx & 15) * 4;            // source word within row
            int dw = r * PAD + w + ((w >> 5) << 2);  // +4 skew for w>=32
            CP16(sAu + dw * 4, g_x1t + (size_t)(n0 + r) * D + w);
            CP16(sBu + dw * 4, g_x2t + (size_t)(m0 + r) * D + w);
        }
        asm volatile("cp.async.commit_group;" ::: "memory");
        asm volatile("cp.async.wait_group 0;" ::: "memory");
    }
    __syncthreads();

    float acc[4][4][4];
#pragma unroll
    for (int i = 0; i < 4; ++i)
#pragma unroll
        for (int j = 0; j < 4; ++j)
#pragma unroll
            for (int c = 0; c < 4; ++c) acc[i][j][c] = 0.f;

    // ---- K loop: 8 steps of k=8, paired LDS.64 fragment loads ----
#pragma unroll
    for (int ks = 0; ks < 8; ++ks) {
        const int kbase = 8 * ks + 4 * (ks >> 2) + 2 * q;

        uint2 bfr[4];                 // .x = k(q), .y = k(q+4)
#pragma unroll
        for (int nf = 0; nf < 4; ++nf)
            bfr[nf] = *(const uint2*)(sb + (wn * 32 + nf * 8 + g) * PAD + kbase);

#pragma unroll
        for (int mf = 0; mf < 4; ++mf) {
            const int r = wm * 64 + mf * 16 + g;
            uint2 alo = *(const uint2*)(sa + r * PAD + kbase);        // a0, a2
            uint2 ahi = *(const uint2*)(sa + (r + 8) * PAD + kbase);  // a1, a3
#pragma unroll
            for (int nf = 0; nf < 4; ++nf) {
                asm volatile(
                    "mma.sync.aligned.m16n8k8.row.col.f32.tf32.tf32.f32 "
                    "{%0,%1,%2,%3}, {%4,%5,%6,%7}, {%8,%9}, {%0,%1,%2,%3};"
                    : "+f"(acc[mf][nf][0]), "+f"(acc[mf][nf][1]),
                      "+f"(acc[mf][nf][2]), "+f"(acc[mf][nf][3])
                    : "r"(alo.x), "r"(ahi.x), "r"(alo.y), "r"(ahi.y),
                      "r"(bfr[nf].x), "r"(bfr[nf].y));
            }
        }
    }

    // ---- epilogue: d2 = max(s1 + s2 - 2*cross, 0), streaming stores ----
#pragma unroll
    for (int mf = 0; mf < 4; ++mf) {
        const int r_lo = n0 + wm * 64 + mf * 16 + g;
        const float s1a = __ldg(&g_sq1[r_lo]);
        const float s1b = __ldg(&g_sq1[r_lo + 8]);
        float* orow_a = out + (size_t)r_lo * M + m0;
        float* orow_b = orow_a + (size_t)8 * M;
#pragma unroll
        for (int nf = 0; nf < 4; ++nf) {
            const int cidx = wn * 32 + nf * 8 + q * 2;
            const float2 s2 = __ldg((const float2*)&g_sq2[m0 + cidx]);
            float2 ra, rb;
            ra.x = fmaxf(fmaf(-2.f, acc[mf][nf][0], s1a + s2.x), 0.f);
            ra.y = fmaxf(fmaf(-2.f, acc[mf][nf][1], s1a + s2.y), 0.f);
            rb.x = fmaxf(fmaf(-2.f, acc[mf][nf][2], s1b + s2.x), 0.f);
            rb.y = fmaxf(fmaf(-2.f, acc[mf][nf][3], s1b + s2.y), 0.f);
            __stcs((float2*)(orow_a + cidx), ra);
            __stcs((float2*)(orow_b + cidx), rb);
        }
    }
}

// ---------------------------------------------------------------------------
extern "C" void kernel_launch(void* const* d_in, const int* in_sizes, int n_in,
                              void* d_out, int out_size) {
    const float* x1 = (const float*)d_in[0];
    const float* x2 = (const float*)d_in[1];
    float* out = (float*)d_out;

    const int N = in_sizes[0] / D;   // 8192
    const int M = in_sizes[1] / D;   // 8192

    const int smem_bytes = 2 * BM * PAD * sizeof(uint32_t);  // 73728
    cudaFuncSetAttribute(dist_kernel,
                         cudaFuncAttributeMaxDynamicSharedMemorySize, smem_bytes);

    prep_kernel<<<2 * NROWS * 32 / 256, 256>>>(x1, x2);

    dim3 grid(M / BN, N / BM);
    dist_kernel<<<grid, 256, smem_bytes>>>(out, M);
}

// round 16
// speedup vs baseline: 1.1194x; 1.0633x over previous
#include <cuda_runtime.h>
#include <cstdint>

#define D    64
#define BM   128
#define BN   128
#define PAD  72          // words; 72 mod 32 == 8 -> conflict-free LDS.64 fragment phases
#define NROWS 8192

__device__ float g_sq1[NROWS];
__device__ float g_sq2[NROWS];
__device__ float g_x1t[NROWS * D];   // tf32-rounded, K-interleaved
__device__ float g_x2t[NROWS * D];

// ---------------------------------------------------------------------------
__device__ __forceinline__ uint32_t f2tf32(float f) {
    uint32_t u;
    asm("cvt.rna.tf32.f32 %0, %1;" : "=r"(u) : "f"(f));
    return u;
}
__device__ __forceinline__ float tf32val(float f) {
    return __uint_as_float(f2tf32(f));
}
__device__ __forceinline__ uint32_t smem_u32(const void* p) {
    uint32_t a;
    asm("{ .reg .u64 t; cvta.to.shared.u64 t, %1; cvt.u32.u64 %0, t; }" : "=r"(a) : "l"(p));
    return a;
}
#define CP16(dst_u32, src_ptr) \
    asm volatile("cp.async.cg.shared.global [%0], [%1], 16;" \
                 :: "r"(dst_u32), "l"(src_ptr) : "memory")

// ---------------------------------------------------------------------------
// Prep: tf32(RNA)-round both inputs into K-interleaved layout + row norms.
// Interleaved word w of a row holds original k = 8*(w>>3) + ((w&7)>>1) + 4*(w&1),
// i.e. per 8-block order [k0,k4,k1,k5,k2,k6,k3,k7] (matches paired LDS.64).
// ---------------------------------------------------------------------------
__global__ void prep_kernel(const float* __restrict__ x1,
                            const float* __restrict__ x2) {
    const int gw = (blockIdx.x * blockDim.x + threadIdx.x) >> 5;  // row id
    const int lane = threadIdx.x & 31;
    const int row = gw & (NROWS - 1);
    const float* src = (gw < NROWS) ? x1 : x2;
    float* dst       = (gw < NROWS) ? g_x1t : g_x2t;
    float* nrm       = (gw < NROWS) ? g_sq1 : g_sq2;

    const int k0 = 8 * (lane >> 2) + (lane & 3);      // lane covers k0, k0+4
    float a = tf32val(src[(size_t)row * D + k0]);
    float b = tf32val(src[(size_t)row * D + k0 + 4]);
    *(float2*)(dst + (size_t)row * D + 2 * lane) = make_float2(a, b);

    float s = fmaf(a, a, b * b);
#pragma unroll
    for (int o = 16; o; o >>= 1)
        s += __shfl_xor_sync(0xFFFFFFFF, s, o);
    if (lane == 0) nrm[row] = s;
}

// ---------------------------------------------------------------------------
// 128x128 tile per CTA, 8 warps (2x4), warp tile 64x32, 2 CTAs/SM.
// Staging: cp.async from pre-converted interleaved arrays.
// Mainloop: paired LDS.64 fragment loads + m16n8k8 tf32 MMA (R13/R15 core).
// Epilogue: warp-private 4KB transpose buffer (no CTA barrier), two 32x32
// passes, swizzle col ^ 8*(row&3) -> dense STG.128 (4 lines/instr).
// ---------------------------------------------------------------------------
__global__ __launch_bounds__(256, 2)
void dist_kernel(float* __restrict__ out, int M) {
    extern __shared__ uint32_t smem[];
    uint32_t* sa = smem;              // [BM][PAD] interleaved tf32 bits
    uint32_t* sb = smem + BM * PAD;   // [BN][PAD]

    const int n0  = blockIdx.y * BM;
    const int m0  = blockIdx.x * BN;
    const int tid = threadIdx.x;
    const int wid = tid >> 5;
    const int lane = tid & 31;
    const int wm = wid >> 2;          // 0..1 : 64-row band
    const int wn = wid & 3;           // 0..3 : 32-col band
    const int g  = lane >> 2;         // 0..7
    const int q  = lane & 3;          // 0..3

    float* buf = (float*)(smem + 2 * BM * PAD) + wid * 1024;  // 32x32 floats

    // ---- stage tiles: 16B cp.async chunks into skewed rows ----
    {
        const uint32_t sAu = smem_u32(sa);
        const uint32_t sBu = smem_u32(sb);
#pragma unroll
        for (int it = 0; it < 8; ++it) {
            int idx = tid + it * 256;          // 0..2047: (row, chunk)
            int r = idx >> 4;
            int w = (idx & 15) * 4;            // source word within row
            int dw = r * PAD + w + ((w >> 5) << 2);  // +4 skew for w>=32
            CP16(sAu + dw * 4, g_x1t + (size_t)(n0 + r) * D + w);
            CP16(sBu + dw * 4, g_x2t + (size_t)(m0 + r) * D + w);
        }
        asm volatile("cp.async.commit_group;" ::: "memory");
        asm volatile("cp.async.wait_group 0;" ::: "memory");
    }
    __syncthreads();

    float acc[4][4][4];
#pragma unroll
    for (int i = 0; i < 4; ++i)
#pragma unroll
        for (int j = 0; j < 4; ++j)
#pragma unroll
            for (int c = 0; c < 4; ++c) acc[i][j][c] = 0.f;

    // ---- K loop: 8 steps of k=8, paired LDS.64 fragment loads ----
#pragma unroll
    for (int ks = 0; ks < 8; ++ks) {
        const int kbase = 8 * ks + 4 * (ks >> 2) + 2 * q;

        uint2 bfr[4];                 // .x = k(q), .y = k(q+4)
#pragma unroll
        for (int nf = 0; nf < 4; ++nf)
            bfr[nf] = *(const uint2*)(sb + (wn * 32 + nf * 8 + g) * PAD + kbase);

#pragma unroll
        for (int mf = 0; mf < 4; ++mf) {
            const int r = wm * 64 + mf * 16 + g;
            uint2 alo = *(const uint2*)(sa + r * PAD + kbase);        // a0, a2
            uint2 ahi = *(const uint2*)(sa + (r + 8) * PAD + kbase);  // a1, a3
#pragma unroll
            for (int nf = 0; nf < 4; ++nf) {
                asm volatile(
                    "mma.sync.aligned.m16n8k8.row.col.f32.tf32.tf32.f32 "
                    "{%0,%1,%2,%3}, {%4,%5,%6,%7}, {%8,%9}, {%0,%1,%2,%3};"
                    : "+f"(acc[mf][nf][0]), "+f"(acc[mf][nf][1]),
                      "+f"(acc[mf][nf][2]), "+f"(acc[mf][nf][3])
                    : "r"(alo.x), "r"(ahi.x), "r"(alo.y), "r"(ahi.y),
                      "r"(bfr[nf].x), "r"(bfr[nf].y));
            }
        }
    }

    // ---- epilogue: two 32x32 transpose passes through warp-private buffer ----
    const int swz = 8 * (g & 3);              // row&3 == g&3 for rows 16mf+g(+8)
    const int rr  = lane >> 3;                // readback: row offset 0..3
    const int jr  = lane & 7;                 // readback: float4 index 0..7

#pragma unroll
    for (int h = 0; h < 2; ++h) {
        // phase 1: d2 -> swizzled buffer (rows 0..31 = mh*16 + g (+8))
#pragma unroll
        for (int mh = 0; mh < 2; ++mh) {
            const int mf = h * 2 + mh;
            const int grow = n0 + wm * 64 + mf * 16 + g;
            const float s1a = __ldg(&g_sq1[grow]);
            const float s1b = __ldg(&g_sq1[grow + 8]);
            const int rl0 = mh * 16 + g;
#pragma unroll
            for (int nf = 0; nf < 4; ++nf) {
                const int cidx = wn * 32 + nf * 8 + 2 * q;
                const float2 s2 = __ldg((const float2*)&g_sq2[m0 + cidx]);
                const int cs = (nf * 8 + 2 * q) ^ swz;
                float2 ra, rb;
                ra.x = fmaxf(fmaf(-2.f, acc[mf][nf][0], s1a + s2.x), 0.f);
                ra.y = fmaxf(fmaf(-2.f, acc[mf][nf][1], s1a + s2.y), 0.f);
                rb.x = fmaxf(fmaf(-2.f, acc[mf][nf][2], s1b + s2.x), 0.f);
                rb.y = fmaxf(fmaf(-2.f, acc[mf][nf][3], s1b + s2.y), 0.f);
                *(float2*)(buf + rl0 * 32 + cs)       = ra;
                *(float2*)(buf + (rl0 + 8) * 32 + cs) = rb;
            }
        }
        __syncwarp();

        // phase 2: de-swizzled readback -> dense STG.128
#pragma unroll
        for (int t = 0; t < 8; ++t) {
            const int rl = t * 4 + rr;        // buffer row 0..31
            const float4 v = *(const float4*)(buf + rl * 32
                                              + ((4 * jr) ^ (8 * (rl & 3))));
            __stcs((float4*)(out + (size_t)(n0 + wm * 64 + h * 32 + rl) * M
                                  + m0 + wn * 32 + 4 * jr), v);
        }
        __syncwarp();   // buffer reused by next pass
    }
}

// ---------------------------------------------------------------------------
extern "C" void kernel_launch(void* const* d_in, const int* in_sizes, int n_in,
                              void* d_out, int out_size) {
    const float* x1 = (const float*)d_in[0];
    const float* x2 = (const float*)d_in[1];
    float* out = (float*)d_out;

    const int N = in_sizes[0] / D;   // 8192
    const int M = in_sizes[1] / D;   // 8192

    const int smem_bytes = 2 * BM * PAD * sizeof(uint32_t)   // 73728
                         + 8 * 1024 * sizeof(float);          // +32768 = 106496
    cudaFuncSetAttribute(dist_kernel,
                         cudaFuncAttributeMaxDynamicSharedMemorySize, smem_bytes);

    prep_kernel<<<2 * NROWS * 32 / 256, 256>>>(x1, x2);

    dim3 grid(M / BN, N / BM);
    dist_kernel<<<grid, 256, smem_bytes>>>(out, M);
}

// round 17
// speedup vs baseline: 1.1306x; 1.0100x over previous
#include <cuda_runtime.h>
#include <cstdint>

#define D    64
#define BM   128
#define BN   128
#define PAD  80          // words; 80 mod 32 == 16 -> conflict-free LDS.128 fragment phases
#define NROWS 8192

__device__ float g_sq1[NROWS];
__device__ float g_sq2[NROWS];
__device__ float g_x1t[NROWS * D];   // tf32-rounded, 2-step K-interleaved
__device__ float g_x2t[NROWS * D];

// ---------------------------------------------------------------------------
__device__ __forceinline__ uint32_t f2tf32(float f) {
    uint32_t u;
    asm("cvt.rna.tf32.f32 %0, %1;" : "=r"(u) : "f"(f));
    return u;
}
__device__ __forceinline__ float tf32val(float f) {
    return __uint_as_float(f2tf32(f));
}
__device__ __forceinline__ uint32_t smem_u32(const void* p) {
    uint32_t a;
    asm("{ .reg .u64 t; cvta.to.shared.u64 t, %1; cvt.u32.u64 %0, t; }" : "=r"(a) : "l"(p));
    return a;
}
#define CP16(dst_u32, src_ptr) \
    asm volatile("cp.async.cg.shared.global [%0], [%1], 16;" \
                 :: "r"(dst_u32), "l"(src_ptr) : "memory")

// ---------------------------------------------------------------------------
// Prep: tf32(RNA)-round both inputs into 2-step K-interleaved layout + norms.
// Word w of a row: b = w>>4, p = w&15  ->  k = 16b + (p>>2) + 4*(p&3)
// so lane q's LDS.128 at word 16b+4q yields {k(q), k(q+4), k(q+8), k(q+12)}.
// ---------------------------------------------------------------------------
__global__ void prep_kernel(const float* __restrict__ x1,
                            const float* __restrict__ x2) {
    const int gw = (blockIdx.x * blockDim.x + threadIdx.x) >> 5;  // row id
    const int lane = threadIdx.x & 31;
    const int row = gw & (NROWS - 1);
    const float* src = (gw < NROWS) ? x1 : x2;
    float* dst       = (gw < NROWS) ? g_x1t : g_x2t;
    float* nrm       = (gw < NROWS) ? g_sq1 : g_sq2;

    float v[2];
#pragma unroll
    for (int j = 0; j < 2; ++j) {
        int w = 2 * lane + j;
        int b = w >> 4, p = w & 15;
        int k = 16 * b + (p >> 2) + 4 * (p & 3);
        v[j] = tf32val(src[(size_t)row * D + k]);
    }
    *(float2*)(dst + (size_t)row * D + 2 * lane) = make_float2(v[0], v[1]);

    float s = fmaf(v[0], v[0], v[1] * v[1]);
#pragma unroll
    for (int o = 16; o; o >>= 1)
        s += __shfl_xor_sync(0xFFFFFFFF, s, o);
    if (lane == 0) nrm[row] = s;
}

// ---------------------------------------------------------------------------
// 128x128 tile per CTA, 8 warps (2x4), warp tile 64x32, 2 CTAs/SM.
// Mainloop: 4 macrosteps of k=16; one LDS.128 per operand row covers two
// m16n8k8 steps (12 LDS.128 + 32 HMMA per macrostep).
// Epilogue: warp-private 4KB transpose buffer -> dense STG.128.
// ---------------------------------------------------------------------------
__global__ __launch_bounds__(256, 2)
void dist_kernel(float* __restrict__ out, int M) {
    extern __shared__ uint32_t smem[];
    uint32_t* sa = smem;              // [BM][PAD] interleaved tf32 bits
    uint32_t* sb = smem + BM * PAD;   // [BN][PAD]

    const int n0  = blockIdx.y * BM;
    const int m0  = blockIdx.x * BN;
    const int tid = threadIdx.x;
    const int wid = tid >> 5;
    const int lane = tid & 31;
    const int wm = wid >> 2;          // 0..1 : 64-row band
    const int wn = wid & 3;           // 0..3 : 32-col band
    const int g  = lane >> 2;         // 0..7
    const int q  = lane & 3;          // 0..3

    float* buf = (float*)(smem + 2 * BM * PAD) + wid * 1024;  // 32x32 floats

    // ---- stage tiles: identity 16B cp.async copies (interleave is global) ----
    {
        const uint32_t sAu = smem_u32(sa);
        const uint32_t sBu = smem_u32(sb);
#pragma unroll
        for (int it = 0; it < 8; ++it) {
            int idx = tid + it * 256;          // 0..2047: (row, chunk)
            int r = idx >> 4;
            int w = (idx & 15) * 4;            // word within row
            uint32_t dw = (uint32_t)(r * PAD + w);
            CP16(sAu + dw * 4, g_x1t + (size_t)(n0 + r) * D + w);
            CP16(sBu + dw * 4, g_x2t + (size_t)(m0 + r) * D + w);
        }
        asm volatile("cp.async.commit_group;" ::: "memory");
        asm volatile("cp.async.wait_group 0;" ::: "memory");
    }
    __syncthreads();

    float acc[4][4][4];
#pragma unroll
    for (int i = 0; i < 4; ++i)
#pragma unroll
        for (int j = 0; j < 4; ++j)
#pragma unroll
            for (int c = 0; c < 4; ++c) acc[i][j][c] = 0.f;

    // ---- K loop: 4 macrosteps of k=16 (two m16n8k8 steps each) ----
#pragma unroll
    for (int m = 0; m < 4; ++m) {
        const int kw = 16 * m + 4 * q;

        uint4 bfr[4];     // .x/.y = step0 (k q, q+4), .z/.w = step1 (k q+8, q+12)
#pragma unroll
        for (int nf = 0; nf < 4; ++nf)
            bfr[nf] = *(const uint4*)(sb + (wn * 32 + nf * 8 + g) * PAD + kw);

#pragma unroll
        for (int mf = 0; mf < 4; ++mf) {
            const int r = wm * 64 + mf * 16 + g;
            uint4 alo = *(const uint4*)(sa + r * PAD + kw);        // row g
            uint4 ahi = *(const uint4*)(sa + (r + 8) * PAD + kw);  // row g+8
#pragma unroll
            for (int nf = 0; nf < 4; ++nf) {
                asm volatile(
                    "mma.sync.aligned.m16n8k8.row.col.f32.tf32.tf32.f32 "
                    "{%0,%1,%2,%3}, {%4,%5,%6,%7}, {%8,%9}, {%0,%1,%2,%3};"
                    : "+f"(acc[mf][nf][0]), "+f"(acc[mf][nf][1]),
                      "+f"(acc[mf][nf][2]), "+f"(acc[mf][nf][3])
                    : "r"(alo.x), "r"(ahi.x), "r"(alo.y), "r"(ahi.y),
                      "r"(bfr[nf].x), "r"(bfr[nf].y));
            }
#pragma unroll
            for (int nf = 0; nf < 4; ++nf) {
                asm volatile(
                    "mma.sync.aligned.m16n8k8.row.col.f32.tf32.tf32.f32 "
                    "{%0,%1,%2,%3}, {%4,%5,%6,%7}, {%8,%9}, {%0,%1,%2,%3};"
                    : "+f"(acc[mf][nf][0]), "+f"(acc[mf][nf][1]),
                      "+f"(acc[mf][nf][2]), "+f"(acc[mf][nf][3])
                    : "r"(alo.z), "r"(ahi.z), "r"(alo.w), "r"(ahi.w),
                      "r"(bfr[nf].z), "r"(bfr[nf].w));
            }
        }
    }

    // ---- epilogue: two 32x32 transpose passes through warp-private buffer ----
    const int swz = 8 * (g & 3);              // row&3 == g&3 for rows 16mf+g(+8)
    const int rr  = lane >> 3;                // readback: row offset 0..3
    const int jr  = lane & 7;                 // readback: float4 index 0..7

#pragma unroll
    for (int h = 0; h < 2; ++h) {
        // phase 1: d2 -> swizzled buffer (rows 0..31 = mh*16 + g (+8))
#pragma unroll
        for (int mh = 0; mh < 2; ++mh) {
            const int mf = h * 2 + mh;
            const int grow = n0 + wm * 64 + mf * 16 + g;
            const float s1a = __ldg(&g_sq1[grow]);
            const float s1b = __ldg(&g_sq1[grow + 8]);
            const int rl0 = mh * 16 + g;
#pragma unroll
            for (int nf = 0; nf < 4; ++nf) {
                const int cidx = wn * 32 + nf * 8 + 2 * q;
                const float2 s2 = __ldg((const float2*)&g_sq2[m0 + cidx]);
                const int cs = (nf * 8 + 2 * q) ^ swz;
                float2 ra, rb;
                ra.x = fmaxf(fmaf(-2.f, acc[mf][nf][0], s1a + s2.x), 0.f);
                ra.y = fmaxf(fmaf(-2.f, acc[mf][nf][1], s1a + s2.y), 0.f);
                rb.x = fmaxf(fmaf(-2.f, acc[mf][nf][2], s1b + s2.x), 0.f);
                rb.y = fmaxf(fmaf(-2.f, acc[mf][nf][3], s1b + s2.y), 0.f);
                *(float2*)(buf + rl0 * 32 + cs)       = ra;
                *(float2*)(buf + (rl0 + 8) * 32 + cs) = rb;
            }
        }
        __syncwarp();

        // phase 2: de-swizzled readback -> dense STG.128
#pragma unroll
        for (int t = 0; t < 8; ++t) {
            const int rl = t * 4 + rr;        // buffer row 0..31
            const float4 v = *(const float4*)(buf + rl * 32
                                              + ((4 * jr) ^ (8 * (rl & 3))));
            __stcs((float4*)(out + (size_t)(n0 + wm * 64 + h * 32 + rl) * M
                                  + m0 + wn * 32 + 4 * jr), v);
        }
        __syncwarp();   // buffer reused by next pass
    }
}

// ---------------------------------------------------------------------------
extern "C" void kernel_launch(void* const* d_in, const int* in_sizes, int n_in,
                              void* d_out, int out_size) {
    const float* x1 = (const float*)d_in[0];
    const float* x2 = (const float*)d_in[1];
    float* out = (float*)d_out;

    const int N = in_sizes[0] / D;   // 8192
    const int M = in_sizes[1] / D;   // 8192

    const int smem_bytes = 2 * BM * PAD * sizeof(uint32_t)   // 81920
                         + 8 * 1024 * sizeof(float);          // +32768 = 114688
    cudaFuncSetAttribute(dist_kernel,
                         cudaFuncAttributeMaxDynamicSharedMemorySize, smem_bytes);

    prep_kernel<<<2 * NROWS * 32 / 256, 256>>>(x1, x2);

    dim3 grid(M / BN, N / BM);
    dist_kernel<<<grid, 256, smem_bytes>>>(out, M);
}